// round 12
// baseline (speedup 1.0000x reference)
#include <cuda_runtime.h>
#include <cstdint>
#include <cstddef>

typedef unsigned long long ull;

#define THREADS 256
#define NEG_SLOPE 0.01f

// ---- weights / bias in constant memory (filled by async D2D memcpy each launch) ----
// cW2[r*8 + tt] = raw row-major [128][32] float data viewed as {f32x2, f32x2}
__constant__ ulonglong2 cWih2[1024];
__constant__ ulonglong2 cWhh2[1024];
__constant__ float      cB[256];       // bih[128] | bhh[128]

__device__ __forceinline__ ull pack2(float lo, float hi) {
    ull r; asm("mov.b64 %0, {%1, %2};" : "=l"(r) : "f"(lo), "f"(hi)); return r;
}
__device__ __forceinline__ void unpack2(ull v, float& lo, float& hi) {
    asm("mov.b64 {%0, %1}, %2;" : "=f"(lo), "=f"(hi) : "l"(v));
}
__device__ __forceinline__ ull fma2(ull a, ull b, ull c) {
    ull d; asm("fma.rn.f32x2 %0, %1, %2, %3;" : "=l"(d) : "l"(a), "l"(b), "l"(c)); return d;
}
__device__ __forceinline__ float sigm_f(float x) {
    return __fdividef(1.0f, 1.0f + __expf(-x));
}
__device__ __forceinline__ float tanh_f(float x) {
    return __fdividef(2.0f, 1.0f + __expf(-2.0f * x)) - 1.0f;
}

// Accumulate 4 gate dot-products for unit u from constant weights (WSEL: 0=Wih, 1=Whh).
// Direct symbol access keeps these as constant-space (LDCU) loads.
template<int WSEL>
__device__ __forceinline__ void gate_accum(int u, const ull* __restrict__ m,
                                           ull& a0, ull& a1, ull& a2, ull& a3)
{
    #pragma unroll
    for (int tt = 0; tt < 8; tt++) {
        ulonglong2 w0 = WSEL ? cWhh2[(u      ) * 8 + tt] : cWih2[(u      ) * 8 + tt];
        ulonglong2 w1 = WSEL ? cWhh2[(u +  32) * 8 + tt] : cWih2[(u +  32) * 8 + tt];
        ulonglong2 w2 = WSEL ? cWhh2[(u +  64) * 8 + tt] : cWih2[(u +  64) * 8 + tt];
        ulonglong2 w3 = WSEL ? cWhh2[(u +  96) * 8 + tt] : cWih2[(u +  96) * 8 + tt];
        a0 = fma2(w0.x, m[2*tt], a0);  a0 = fma2(w0.y, m[2*tt+1], a0);
        a1 = fma2(w1.x, m[2*tt], a1);  a1 = fma2(w1.y, m[2*tt+1], a1);
        a2 = fma2(w2.x, m[2*tt], a2);  a2 = fma2(w2.y, m[2*tt+1], a2);
        a3 = fma2(w3.x, m[2*tt], a3);  a3 = fma2(w3.y, m[2*tt+1], a3);
    }
}

__global__ __launch_bounds__(THREADS, 1)
void lstm4_reg(const float* __restrict__ x,
               const float* __restrict__ h0,
               const float* __restrict__ c0,
               float* __restrict__ out, int n)
{
    const int e = blockIdx.x * THREADS + threadIdx.x;
    if (e >= n) return;

    ull m[16];                       // packed source vector (x, then h)

    // ---- load x row (streaming) ----
    {
        const float4* xr = (const float4*)(x + (size_t)e * 32);
        #pragma unroll
        for (int q = 0; q < 8; q++) {
            float4 a = __ldcs(xr + q);
            m[2*q]   = ((ull*)&a)[0];
            m[2*q+1] = ((ull*)&a)[1];
        }
    }

    // ---- x-pass: xg[4u+{0..3}] = bias + x @ Wih^T rows {u, u+32, u+64, u+96} ----
    float xg[128];                   // entire x_gates vector in registers
    #pragma unroll
    for (int u = 0; u < 32; u++) {
        ull a0 = 0ull, a1 = 0ull, a2 = 0ull, a3 = 0ull;
        gate_accum<0>(u, m, a0, a1, a2, a3);
        float lo, hi;
        unpack2(a0, lo, hi); xg[4*u + 0] = lo + hi + cB[u      ] + cB[128 + u      ];
        unpack2(a1, lo, hi); xg[4*u + 1] = lo + hi + cB[u +  32] + cB[128 + u +  32];
        unpack2(a2, lo, hi); xg[4*u + 2] = lo + hi + cB[u +  64] + cB[128 + u +  64];
        unpack2(a3, lo, hi); xg[4*u + 3] = lo + hi + cB[u +  96] + cB[128 + u +  96];
    }

    // ---- load h0 into packed regs (streaming), c0 into cl ----
    {
        const float4* hr = (const float4*)(h0 + (size_t)e * 32);
        #pragma unroll
        for (int q = 0; q < 8; q++) {
            float4 a = __ldcs(hr + q);
            m[2*q]   = ((ull*)&a)[0];
            m[2*q+1] = ((ull*)&a)[1];
        }
    }
    float cl[32], hn[32];
    {
        const float4* cr = (const float4*)(c0 + (size_t)e * 32);
        #pragma unroll
        for (int q = 0; q < 8; q++) {
            float4 a = __ldcs(cr + q);
            cl[4*q] = a.x; cl[4*q+1] = a.y; cl[4*q+2] = a.z; cl[4*q+3] = a.w;
        }
    }

    // ---- 4 recurrent steps (s-loop rolled to bound code size) ----
    #pragma unroll 1
    for (int s = 0; s < 4; s++) {
        #pragma unroll
        for (int u = 0; u < 32; u++) {
            ull a0 = 0ull, a1 = 0ull, a2 = 0ull, a3 = 0ull;
            gate_accum<1>(u, m, a0, a1, a2, a3);
            float lo, hi;
            float gi, gf, gg, go;
            unpack2(a0, lo, hi); gi = lo + hi + xg[4*u + 0];
            unpack2(a1, lo, hi); gf = lo + hi + xg[4*u + 1];
            unpack2(a2, lo, hi); gg = lo + hi + xg[4*u + 2];
            unpack2(a3, lo, hi); go = lo + hi + xg[4*u + 3];
            float ig = sigm_f(gi), fg = sigm_f(gf);
            float gt = tanh_f(gg), og = sigm_f(go);
            float cn = fmaf(fg, cl[u], ig * gt);
            cl[u] = cn;
            float hv = og * tanh_f(cn);
            hn[u] = (hv >= 0.0f) ? hv : NEG_SLOPE * hv;   // LeakyReLU each step
        }
        if (s < 3) {
            #pragma unroll
            for (int t = 0; t < 16; t++) m[t] = pack2(hn[2*t], hn[2*t + 1]);
        }
    }

    // ---- store final h (streaming) ----
    {
        float4* go4 = (float4*)(out + (size_t)e * 32);
        #pragma unroll
        for (int q = 0; q < 8; q++) {
            float4 v = make_float4(hn[4*q], hn[4*q+1], hn[4*q+2], hn[4*q+3]);
            __stcs(go4 + q, v);
        }
    }
}

extern "C" void kernel_launch(void* const* d_in, const int* in_sizes, int n_in,
                              void* d_out, int out_size)
{
    const float* x   = (const float*)d_in[0];   // token_embedding [B,32]
    const float* h0  = (const float*)d_in[1];   // hx0 [B,32]
    const float* c0  = (const float*)d_in[2];   // cx0 [B,32]
    float* out = (float*)d_out;

    // weights + biases -> constant memory (D2D async, graph-capturable)
    cudaMemcpyToSymbolAsync(cWih2, d_in[3], 128 * 32 * sizeof(float), 0,
                            cudaMemcpyDeviceToDevice, 0);
    cudaMemcpyToSymbolAsync(cWhh2, d_in[4], 128 * 32 * sizeof(float), 0,
                            cudaMemcpyDeviceToDevice, 0);
    cudaMemcpyToSymbolAsync(cB,    d_in[5], 128 * sizeof(float), 0,
                            cudaMemcpyDeviceToDevice, 0);
    cudaMemcpyToSymbolAsync(cB,    d_in[6], 128 * sizeof(float), 128 * sizeof(float),
                            cudaMemcpyDeviceToDevice, 0);

    int n = in_sizes[0] / 32;                   // batch B
    int grid = (n + THREADS - 1) / THREADS;
    lstm4_reg<<<grid, THREADS>>>(x, h0, c0, out, n);
}

// round 14
// speedup vs baseline: 1.6639x; 1.6639x over previous
#include <cuda_runtime.h>
#include <cstdint>
#include <cstddef>

typedef unsigned long long ull;

#define THREADS 128
#define NEG_SLOPE 0.01f
#define XG_BYTES (THREADS * 128 * sizeof(float))   // 64 KB per CTA

// ---- weights / bias in constant memory (filled by async D2D memcpy each launch) ----
// cW2[r*8 + tt] = raw row-major [128][32] float data viewed as {f32x2, f32x2}
__constant__ ulonglong2 cWih2[1024];
__constant__ ulonglong2 cWhh2[1024];
__constant__ float      cB[256];       // bih[128] | bhh[128]

__device__ __forceinline__ ull pack2(float lo, float hi) {
    ull r; asm("mov.b64 %0, {%1, %2};" : "=l"(r) : "f"(lo), "f"(hi)); return r;
}
__device__ __forceinline__ void unpack2(ull v, float& lo, float& hi) {
    asm("mov.b64 {%0, %1}, %2;" : "=f"(lo), "=f"(hi) : "l"(v));
}
__device__ __forceinline__ ull fma2(ull a, ull b, ull c) {
    ull d; asm("fma.rn.f32x2 %0, %1, %2, %3;" : "=l"(d) : "l"(a), "l"(b), "l"(c)); return d;
}
__device__ __forceinline__ float sigm_f(float x) {
    return __fdividef(1.0f, 1.0f + __expf(-x));
}
__device__ __forceinline__ float tanh_f(float x) {
    return __fdividef(2.0f, 1.0f + __expf(-2.0f * x)) - 1.0f;
}

// Accumulate 4 gate dot-products for unit u (WSEL: 0=Wih, 1=Whh) via LDCU.128.
template<int WSEL>
__device__ __forceinline__ void gate_accum(int u, const ull* __restrict__ m,
                                           ull& a0, ull& a1, ull& a2, ull& a3)
{
    #pragma unroll
    for (int tt = 0; tt < 8; tt++) {
        ulonglong2 w0 = WSEL ? cWhh2[(u      ) * 8 + tt] : cWih2[(u      ) * 8 + tt];
        ulonglong2 w1 = WSEL ? cWhh2[(u +  32) * 8 + tt] : cWih2[(u +  32) * 8 + tt];
        ulonglong2 w2 = WSEL ? cWhh2[(u +  64) * 8 + tt] : cWih2[(u +  64) * 8 + tt];
        ulonglong2 w3 = WSEL ? cWhh2[(u +  96) * 8 + tt] : cWih2[(u +  96) * 8 + tt];
        a0 = fma2(w0.x, m[2*tt], a0);  a0 = fma2(w0.y, m[2*tt+1], a0);
        a1 = fma2(w1.x, m[2*tt], a1);  a1 = fma2(w1.y, m[2*tt+1], a1);
        a2 = fma2(w2.x, m[2*tt], a2);  a2 = fma2(w2.y, m[2*tt+1], a2);
        a3 = fma2(w3.x, m[2*tt], a3);  a3 = fma2(w3.y, m[2*tt+1], a3);
    }
}

__global__ __launch_bounds__(THREADS, 3)
void lstm4_smem(const float* __restrict__ x,
                const float* __restrict__ h0,
                const float* __restrict__ c0,
                float* __restrict__ out, int n)
{
    extern __shared__ float4 xs[];      // [u][tid] -> 32 * 128 float4 = 64 KB
    const int tid = threadIdx.x;
    const int e   = blockIdx.x * THREADS + tid;
    if (e >= n) return;                 // no barriers anywhere -> safe early exit

    ull m[16];                          // packed source vector (x, then h)

    // ---- load x row (streaming) ----
    {
        const float4* xr = (const float4*)(x + (size_t)e * 32);
        #pragma unroll
        for (int q = 0; q < 8; q++) {
            float4 a = __ldcs(xr + q);
            m[2*q]   = ((ull*)&a)[0];
            m[2*q+1] = ((ull*)&a)[1];
        }
    }

    // ---- x-pass: xs[u][tid] = bias + x @ Wih^T rows {u, u+32, u+64, u+96} ----
    #pragma unroll 1
    for (int u = 0; u < 32; u++) {
        ull a0 = 0ull, a1 = 0ull, a2 = 0ull, a3 = 0ull;
        gate_accum<0>(u, m, a0, a1, a2, a3);
        float lo, hi; float4 g;
        unpack2(a0, lo, hi); g.x = lo + hi + cB[u      ] + cB[128 + u      ];
        unpack2(a1, lo, hi); g.y = lo + hi + cB[u +  32] + cB[128 + u +  32];
        unpack2(a2, lo, hi); g.z = lo + hi + cB[u +  64] + cB[128 + u +  64];
        unpack2(a3, lo, hi); g.w = lo + hi + cB[u +  96] + cB[128 + u +  96];
        xs[u * THREADS + tid] = g;      // conflict-free STS.128
    }

    // ---- load h0 into packed regs (streaming), c0 into cl ----
    {
        const float4* hr = (const float4*)(h0 + (size_t)e * 32);
        #pragma unroll
        for (int q = 0; q < 8; q++) {
            float4 a = __ldcs(hr + q);
            m[2*q]   = ((ull*)&a)[0];
            m[2*q+1] = ((ull*)&a)[1];
        }
    }
    float cl[32], hn[32];
    {
        const float4* cr = (const float4*)(c0 + (size_t)e * 32);
        #pragma unroll
        for (int q = 0; q < 8; q++) {
            float4 a = __ldcs(cr + q);
            cl[4*q] = a.x; cl[4*q+1] = a.y; cl[4*q+2] = a.z; cl[4*q+3] = a.w;
        }
    }

    // ---- 4 recurrent steps ----
    #pragma unroll 1
    for (int s = 0; s < 4; s++) {
        #pragma unroll 1
        for (int u = 0; u < 32; u++) {
            ull a0 = 0ull, a1 = 0ull, a2 = 0ull, a3 = 0ull;
            gate_accum<1>(u, m, a0, a1, a2, a3);
            float4 xgc = xs[u * THREADS + tid];     // conflict-free LDS.128
            float lo, hi, gi, gf, gg, go;
            unpack2(a0, lo, hi); gi = lo + hi + xgc.x;
            unpack2(a1, lo, hi); gf = lo + hi + xgc.y;
            unpack2(a2, lo, hi); gg = lo + hi + xgc.z;
            unpack2(a3, lo, hi); go = lo + hi + xgc.w;
            float ig = sigm_f(gi), fg = sigm_f(gf);
            float gt = tanh_f(gg), og = sigm_f(go);
            float cn = fmaf(fg, cl[u], ig * gt);
            cl[u] = cn;
            float hv = og * tanh_f(cn);
            hn[u] = (hv >= 0.0f) ? hv : NEG_SLOPE * hv;   // LeakyReLU each step
        }
        if (s < 3) {
            #pragma unroll
            for (int t = 0; t < 16; t++) m[t] = pack2(hn[2*t], hn[2*t + 1]);
        }
    }

    // ---- store final h (streaming) ----
    {
        float4* go4 = (float4*)(out + (size_t)e * 32);
        #pragma unroll
        for (int q = 0; q < 8; q++) {
            float4 v = make_float4(hn[4*q], hn[4*q+1], hn[4*q+2], hn[4*q+3]);
            __stcs(go4 + q, v);
        }
    }
}

extern "C" void kernel_launch(void* const* d_in, const int* in_sizes, int n_in,
                              void* d_out, int out_size)
{
    const float* x   = (const float*)d_in[0];   // token_embedding [B,32]
    const float* h0  = (const float*)d_in[1];   // hx0 [B,32]
    const float* c0  = (const float*)d_in[2];   // cx0 [B,32]
    float* out = (float*)d_out;

    // weights + biases -> constant memory (D2D async, graph-capturable)
    cudaMemcpyToSymbolAsync(cWih2, d_in[3], 128 * 32 * sizeof(float), 0,
                            cudaMemcpyDeviceToDevice, 0);
    cudaMemcpyToSymbolAsync(cWhh2, d_in[4], 128 * 32 * sizeof(float), 0,
                            cudaMemcpyDeviceToDevice, 0);
    cudaMemcpyToSymbolAsync(cB,    d_in[5], 128 * sizeof(float), 0,
                            cudaMemcpyDeviceToDevice, 0);
    cudaMemcpyToSymbolAsync(cB,    d_in[6], 128 * sizeof(float), 128 * sizeof(float),
                            cudaMemcpyDeviceToDevice, 0);

    static int attr_set = 0;
    if (!attr_set) {
        cudaFuncSetAttribute(lstm4_smem,
                             cudaFuncAttributeMaxDynamicSharedMemorySize, XG_BYTES);
        attr_set = 1;
    }

    int n = in_sizes[0] / 32;                   // batch B
    int grid = (n + THREADS - 1) / THREADS;
    lstm4_smem<<<grid, THREADS, XG_BYTES>>>(x, h0, c0, out, n);
}

// round 17
// speedup vs baseline: 2.2265x; 1.3381x over previous
#include <cuda_runtime.h>
#include <cuda_fp16.h>
#include <cstdint>
#include <cstddef>

typedef unsigned long long ull;

#define NELEM   2097152            // B for this problem (scratch stride)
#define THREADS 256
#define NEG_SLOPE 0.01f

// ---- weights / bias in constant memory (filled by async D2D memcpy each launch) ----
__constant__ ulonglong2 cWih2[1024];   // raw [128][32] floats reinterpreted as f32x2 pairs
__constant__ ulonglong2 cWhh2[1024];
__constant__ float      cB[256];       // bih[128] | bhh[128]

// ---- x_gates scratch: [unit u][elem e] uint2 = {half2(gi,gf), half2(gg,go)}  (0.5 GB) ----
__device__ uint2 xg_scratch[(size_t)32 * NELEM];

__device__ __forceinline__ void unpack2(ull v, float& lo, float& hi) {
    asm("mov.b64 {%0, %1}, %2;" : "=f"(lo), "=f"(hi) : "l"(v));
}
__device__ __forceinline__ ull fma2(ull a, ull b, ull c) {
    ull d; asm("fma.rn.f32x2 %0, %1, %2, %3;" : "=l"(d) : "l"(a), "l"(b), "l"(c)); return d;
}
__device__ __forceinline__ float sigm_f(float x) {
    return __fdividef(1.0f, 1.0f + __expf(-x));
}
__device__ __forceinline__ float tanh_f(float x) {
    return __fdividef(2.0f, 1.0f + __expf(-2.0f * x)) - 1.0f;
}

// ---- L2 evict_last cache-policy helpers (keep xg_scratch resident in L2) ----
__device__ __forceinline__ ull mk_evict_last() {
    ull p; asm("createpolicy.fractional.L2::evict_last.b64 %0, 1.0;" : "=l"(p));
    return p;
}
__device__ __forceinline__ uint2 ldg_pol2(const uint2* a, ull pol) {
    uint2 v;
    asm volatile("ld.global.L2::cache_hint.v2.u32 {%0,%1}, [%2], %3;"
                 : "=r"(v.x), "=r"(v.y) : "l"(a), "l"(pol));
    return v;
}
__device__ __forceinline__ void stg_pol2(uint2* a, uint2 v, ull pol) {
    asm volatile("st.global.L2::cache_hint.v2.u32 [%0], {%1,%2}, %3;"
                 :: "l"(a), "r"(v.x), "r"(v.y), "l"(pol) : "memory");
}

// pack 4 gate floats -> {half2, half2}
__device__ __forceinline__ uint2 pack_xg(float gi, float gf, float gg, float go) {
    uint2 r;
    __half2 a = __floats2half2_rn(gi, gf);
    __half2 b = __floats2half2_rn(gg, go);
    r.x = *(uint32_t*)&a;
    r.y = *(uint32_t*)&b;
    return r;
}
// unpack {half2, half2} -> 4 floats
__device__ __forceinline__ void unpack_xg(uint2 v, float& gi, float& gf, float& gg, float& go) {
    __half2 a = *(__half2*)&v.x;
    __half2 b = *(__half2*)&v.y;
    float2 fa = __half22float2(a);
    float2 fb = __half22float2(b);
    gi = fa.x; gf = fa.y; gg = fb.x; go = fb.y;
}

__global__ __launch_bounds__(THREADS, 2)
void lstm4_f16xg(const float* __restrict__ x,
                 const float* __restrict__ h0,
                 const float* __restrict__ c0,
                 float* __restrict__ out, int n)
{
    const int half = (n + 1) >> 1;
    const int e0 = blockIdx.x * THREADS + threadIdx.x;
    if (e0 >= half) return;
    const int  e1   = e0 + half;
    const bool has1 = (e1 < n);
    const int  e1r  = has1 ? e1 : e0;      // safe mirror for loads

    const ull pol = mk_evict_last();

    ull m0[16], m1[16];                    // packed source vectors for both elements

    // ---- load x rows (streaming) ----
    {
        const float4* xr0 = (const float4*)(x + (size_t)e0 * 32);
        const float4* xr1 = (const float4*)(x + (size_t)e1r * 32);
        #pragma unroll
        for (int q = 0; q < 8; q++) {
            float4 a = __ldcs(xr0 + q);
            m0[2*q]   = ((ull*)&a)[0]; m0[2*q+1] = ((ull*)&a)[1];
            float4 b = __ldcs(xr1 + q);
            m1[2*q]   = ((ull*)&b)[0]; m1[2*q+1] = ((ull*)&b)[1];
        }
    }

    // ---- x-pass: xg[u] = bias + x @ Wih^T rows {u, 32+u, 64+u, 96+u} ----
    #pragma unroll 1
    for (int u = 0; u < 32; u++) {
        ull a0=0ull,a1=0ull,a2=0ull,a3=0ull;     // elem0
        ull c0a=0ull,c1a=0ull,c2a=0ull,c3a=0ull; // elem1
        #pragma unroll
        for (int tt = 0; tt < 8; tt++) {
            ulonglong2 w0 = cWih2[(u      ) * 8 + tt];
            ulonglong2 w1 = cWih2[(u +  32) * 8 + tt];
            ulonglong2 w2 = cWih2[(u +  64) * 8 + tt];
            ulonglong2 w3 = cWih2[(u +  96) * 8 + tt];
            a0  = fma2(w0.x, m0[2*tt], a0);  a0  = fma2(w0.y, m0[2*tt+1], a0);
            a1  = fma2(w1.x, m0[2*tt], a1);  a1  = fma2(w1.y, m0[2*tt+1], a1);
            a2  = fma2(w2.x, m0[2*tt], a2);  a2  = fma2(w2.y, m0[2*tt+1], a2);
            a3  = fma2(w3.x, m0[2*tt], a3);  a3  = fma2(w3.y, m0[2*tt+1], a3);
            c0a = fma2(w0.x, m1[2*tt], c0a); c0a = fma2(w0.y, m1[2*tt+1], c0a);
            c1a = fma2(w1.x, m1[2*tt], c1a); c1a = fma2(w1.y, m1[2*tt+1], c1a);
            c2a = fma2(w2.x, m1[2*tt], c2a); c2a = fma2(w2.y, m1[2*tt+1], c2a);
            c3a = fma2(w3.x, m1[2*tt], c3a); c3a = fma2(w3.y, m1[2*tt+1], c3a);
        }
        float bi = cB[u] + cB[128+u];
        float bf = cB[u+32] + cB[128+u+32];
        float bg = cB[u+64] + cB[128+u+64];
        float bo = cB[u+96] + cB[128+u+96];
        float lo, hi, gi, gf, gg, go;
        unpack2(a0, lo, hi); gi = lo + hi + bi;
        unpack2(a1, lo, hi); gf = lo + hi + bf;
        unpack2(a2, lo, hi); gg = lo + hi + bg;
        unpack2(a3, lo, hi); go = lo + hi + bo;
        stg_pol2(&xg_scratch[(size_t)u * NELEM + e0], pack_xg(gi, gf, gg, go), pol);
        unpack2(c0a, lo, hi); gi = lo + hi + bi;
        unpack2(c1a, lo, hi); gf = lo + hi + bf;
        unpack2(c2a, lo, hi); gg = lo + hi + bg;
        unpack2(c3a, lo, hi); go = lo + hi + bo;
        if (has1) stg_pol2(&xg_scratch[(size_t)u * NELEM + e1], pack_xg(gi, gf, gg, go), pol);
    }

    // ---- load h0 into packed regs (streaming), c0 into local ----
    {
        const float4* hr0 = (const float4*)(h0 + (size_t)e0 * 32);
        const float4* hr1 = (const float4*)(h0 + (size_t)e1r * 32);
        #pragma unroll
        for (int q = 0; q < 8; q++) {
            float4 a = __ldcs(hr0 + q);
            m0[2*q]   = ((ull*)&a)[0]; m0[2*q+1] = ((ull*)&a)[1];
            float4 b = __ldcs(hr1 + q);
            m1[2*q]   = ((ull*)&b)[0]; m1[2*q+1] = ((ull*)&b)[1];
        }
    }
    __align__(16) float cl0[32], cl1[32], hn0[32], hn1[32];
    {
        const float4* cr0 = (const float4*)(c0 + (size_t)e0 * 32);
        const float4* cr1 = (const float4*)(c0 + (size_t)e1r * 32);
        #pragma unroll
        for (int q = 0; q < 8; q++) {
            ((float4*)cl0)[q] = __ldcs(cr0 + q);
            ((float4*)cl1)[q] = __ldcs(cr1 + q);
        }
    }

    // ---- 4 recurrent steps ----
    for (int s = 0; s < 4; s++) {
        // prefetch-pipelined xg reads (L2-resident)
        uint2 xga = ldg_pol2(&xg_scratch[(size_t)0 * NELEM + e0], pol);
        uint2 xgb = ldg_pol2(&xg_scratch[(size_t)0 * NELEM + e1r], pol);
        #pragma unroll 1
        for (int u = 0; u < 32; u++) {
            uint2 nxga, nxgb;
            if (u < 31) {
                nxga = ldg_pol2(&xg_scratch[(size_t)(u+1) * NELEM + e0], pol);
                nxgb = ldg_pol2(&xg_scratch[(size_t)(u+1) * NELEM + e1r], pol);
            }
            ull a0=0ull,a1=0ull,a2=0ull,a3=0ull;
            ull c0a=0ull,c1a=0ull,c2a=0ull,c3a=0ull;
            #pragma unroll
            for (int tt = 0; tt < 8; tt++) {
                ulonglong2 w0 = cWhh2[(u      ) * 8 + tt];
                ulonglong2 w1 = cWhh2[(u +  32) * 8 + tt];
                ulonglong2 w2 = cWhh2[(u +  64) * 8 + tt];
                ulonglong2 w3 = cWhh2[(u +  96) * 8 + tt];
                a0  = fma2(w0.x, m0[2*tt], a0);  a0  = fma2(w0.y, m0[2*tt+1], a0);
                a1  = fma2(w1.x, m0[2*tt], a1);  a1  = fma2(w1.y, m0[2*tt+1], a1);
                a2  = fma2(w2.x, m0[2*tt], a2);  a2  = fma2(w2.y, m0[2*tt+1], a2);
                a3  = fma2(w3.x, m0[2*tt], a3);  a3  = fma2(w3.y, m0[2*tt+1], a3);
                c0a = fma2(w0.x, m1[2*tt], c0a); c0a = fma2(w0.y, m1[2*tt+1], c0a);
                c1a = fma2(w1.x, m1[2*tt], c1a); c1a = fma2(w1.y, m1[2*tt+1], c1a);
                c2a = fma2(w2.x, m1[2*tt], c2a); c2a = fma2(w2.y, m1[2*tt+1], c2a);
                c3a = fma2(w3.x, m1[2*tt], c3a); c3a = fma2(w3.y, m1[2*tt+1], c3a);
            }
            float lo, hi, gi, gf, gg, go;
            float xi, xf, xg_, xo;
            // elem 0
            unpack_xg(xga, xi, xf, xg_, xo);
            unpack2(a0, lo, hi); gi = lo + hi + xi;
            unpack2(a1, lo, hi); gf = lo + hi + xf;
            unpack2(a2, lo, hi); gg = lo + hi + xg_;
            unpack2(a3, lo, hi); go = lo + hi + xo;
            {
                float ig = sigm_f(gi), fg = sigm_f(gf);
                float gt = tanh_f(gg), og = sigm_f(go);
                float cn = fmaf(fg, cl0[u], ig * gt);
                cl0[u] = cn;
                float hv = og * tanh_f(cn);
                hn0[u] = (hv >= 0.0f) ? hv : NEG_SLOPE * hv;
            }
            // elem 1
            unpack_xg(xgb, xi, xf, xg_, xo);
            unpack2(c0a, lo, hi); gi = lo + hi + xi;
            unpack2(c1a, lo, hi); gf = lo + hi + xf;
            unpack2(c2a, lo, hi); gg = lo + hi + xg_;
            unpack2(c3a, lo, hi); go = lo + hi + xo;
            {
                float ig = sigm_f(gi), fg = sigm_f(gf);
                float gt = tanh_f(gg), og = sigm_f(go);
                float cn = fmaf(fg, cl1[u], ig * gt);
                cl1[u] = cn;
                float hv = og * tanh_f(cn);
                hn1[u] = (hv >= 0.0f) ? hv : NEG_SLOPE * hv;
            }
            xga = nxga; xgb = nxgb;
        }
        if (s < 3) {
            #pragma unroll
            for (int q = 0; q < 8; q++) {
                ulonglong2 v0 = ((const ulonglong2*)hn0)[q];
                m0[2*q] = v0.x; m0[2*q+1] = v0.y;
                ulonglong2 v1 = ((const ulonglong2*)hn1)[q];
                m1[2*q] = v1.x; m1[2*q+1] = v1.y;
            }
        }
    }

    // ---- store final h (streaming) ----
    {
        float4* go0 = (float4*)(out + (size_t)e0 * 32);
        #pragma unroll
        for (int q = 0; q < 8; q++) __stcs(go0 + q, ((const float4*)hn0)[q]);
        if (has1) {
            float4* go1 = (float4*)(out + (size_t)e1 * 32);
            #pragma unroll
            for (int q = 0; q < 8; q++) __stcs(go1 + q, ((const float4*)hn1)[q]);
        }
    }
}

extern "C" void kernel_launch(void* const* d_in, const int* in_sizes, int n_in,
                              void* d_out, int out_size)
{
    const float* x   = (const float*)d_in[0];   // token_embedding [B,32]
    const float* h0  = (const float*)d_in[1];   // hx0 [B,32]
    const float* c0  = (const float*)d_in[2];   // cx0 [B,32]
    float* out = (float*)d_out;

    // weights + biases -> constant memory (D2D async, graph-capturable)
    cudaMemcpyToSymbolAsync(cWih2, d_in[3], 128 * 32 * sizeof(float), 0,
                            cudaMemcpyDeviceToDevice, 0);
    cudaMemcpyToSymbolAsync(cWhh2, d_in[4], 128 * 32 * sizeof(float), 0,
                            cudaMemcpyDeviceToDevice, 0);
    cudaMemcpyToSymbolAsync(cB,    d_in[5], 128 * sizeof(float), 0,
                            cudaMemcpyDeviceToDevice, 0);
    cudaMemcpyToSymbolAsync(cB,    d_in[6], 128 * sizeof(float), 128 * sizeof(float),
                            cudaMemcpyDeviceToDevice, 0);

    int n = in_sizes[0] / 32;                   // batch B
    int half = (n + 1) >> 1;
    int grid = (half + THREADS - 1) / THREADS;
    lstm4_f16xg<<<grid, THREADS>>>(x, h0, c0, out, n);
}